// round 16
// baseline (speedup 1.0000x reference)
#include <cuda_runtime.h>
#include <cuda_fp16.h>
#include <cstdint>

#define SEQ 384
#define CIN 512
#define HW  64
#define NH  8
#define HD  64
#define K9  (CIN * 9)        // 4608
#define BP  512              // NH * HW batch-pairs
#define NROWS (SEQ * HW)     // 24576 GEMM rows
#define SS2 (SEQ * SEQ)      // 147456

// Scratch (device globals; no runtime allocation)
__device__ __half   g_feats_h[(size_t)4 * BP * SEQ * HD];   // [e][bp][n][dd] hi plane
__device__ __half   g_feats_l[(size_t)4 * BP * SEQ * HD];   // lo plane
__device__ __half   g_vT_h[(size_t)BP * HD * SEQ];          // [bp][dd][n] hi
__device__ __half   g_vT_l[(size_t)BP * HD * SEQ];          // lo
__device__ uint32_t g_attn[(size_t)BP * SS2];               // v=0 a_same storage, packed
__device__ uint32_t g_c2_hl[(size_t)SEQ * CIN * HW];        // conv2 input, packed(hi,lo)
__device__ __half   g_Ah[(size_t)NROWS * K9];               // im2col hi plane (k' = r*512+ci)
__device__ __half   g_Al[(size_t)NROWS * K9];               // im2col lo plane
__device__ __half   g_wh_in[(size_t)2560 * K9];             // weights hi, k'-order
__device__ __half   g_wl_in[(size_t)2560 * K9];
__device__ __half   g_wh_out[(size_t)512 * K9];
__device__ __half   g_wl_out[(size_t)512 * K9];

// ---------------------------------------------------------------------------
// helpers
// ---------------------------------------------------------------------------
__device__ __forceinline__ uint32_t split_h2(float x)
{
    __half hi = __float2half_rn(x);
    __half lo = __float2half_rn(x - __half2float(hi));
    return (uint32_t)__half_as_ushort(hi) | ((uint32_t)__half_as_ushort(lo) << 16);
}
__device__ __forceinline__ float unsplit_h2(uint32_t p)
{
    return __half2float(__ushort_as_half((unsigned short)(p & 0xFFFF)))
         + __half2float(__ushort_as_half((unsigned short)(p >> 16)));
}

__device__ __forceinline__ void mma_f16(float c[4], const uint32_t a[4],
                                        uint32_t b0, uint32_t b1)
{
    asm volatile(
        "mma.sync.aligned.m16n8k16.row.col.f32.f16.f16.f32 "
        "{%0,%1,%2,%3}, {%4,%5,%6,%7}, {%8,%9}, {%0,%1,%2,%3};"
        : "+f"(c[0]), "+f"(c[1]), "+f"(c[2]), "+f"(c[3])
        : "r"(a[0]), "r"(a[1]), "r"(a[2]), "r"(a[3]), "r"(b0), "r"(b1));
}
__device__ __forceinline__ void ldsm4(uint32_t& r0, uint32_t& r1, uint32_t& r2,
                                      uint32_t& r3, uint32_t addr)
{
    asm volatile("ldmatrix.sync.aligned.m8n8.x4.shared.b16 {%0,%1,%2,%3}, [%4];"
                 : "=r"(r0), "=r"(r1), "=r"(r2), "=r"(r3) : "r"(addr));
}
__device__ __forceinline__ void cpa16(uint32_t dst, const void* src)
{
    asm volatile("cp.async.cg.shared.global [%0], [%1], 16;" :: "r"(dst), "l"(src));
}

// ---------------------------------------------------------------------------
// Weight split + permute to k' = r*512 + ci order
// ---------------------------------------------------------------------------
__global__ void split_w_kernel(const float* __restrict__ w,
                               __half* __restrict__ wh, __half* __restrict__ wl, int n)
{
    int i = blockIdx.x * 256 + threadIdx.x;
    if (i >= n) return;
    int co = i / K9;
    int kn = i - co * K9;
    int r = kn >> 9, ci = kn & 511;
    float x = w[(size_t)co * K9 + ci * 9 + r];
    __half hi = __float2half_rn(x);
    wh[i] = hi;
    wl[i] = __float2half_rn(x - __half2float(hi));
}

// ---------------------------------------------------------------------------
// im2col expansion into hi/lo fp16 planes, k' = r*512 + ci.
// ---------------------------------------------------------------------------
template <bool PACKED>
__global__ __launch_bounds__(256) void im2col_kernel(const float* __restrict__ srcF)
{
    __shared__ ushort th[64][72];
    __shared__ ushort tl[64][72];
    const int n   = blockIdx.x;
    const int ci0 = blockIdx.y * 64;
    const int t   = threadIdx.x;

    {
        int sp4 = (t & 15) * 4;
        int ciL = t >> 4;
        #pragma unroll
        for (int pass = 0; pass < 4; pass++) {
            int ci = pass * 16 + ciL;
            if (PACKED) {
                uint4 w = *(const uint4*)(g_c2_hl + ((size_t)n * CIN + ci0 + ci) * 64 + sp4);
                uint32_t ws[4] = {w.x, w.y, w.z, w.w};
                #pragma unroll
                for (int j = 0; j < 4; j++) {
                    th[sp4 + j][ci] = (ushort)(ws[j] & 0xFFFF);
                    tl[sp4 + j][ci] = (ushort)(ws[j] >> 16);
                }
            } else {
                float4 v = *(const float4*)(srcF + ((size_t)n * CIN + ci0 + ci) * 64 + sp4);
                float vs[4] = {v.x, v.y, v.z, v.w};
                #pragma unroll
                for (int j = 0; j < 4; j++) {
                    __half hi = __float2half_rn(vs[j]);
                    __half lo = __float2half_rn(vs[j] - __half2float(hi));
                    th[sp4 + j][ci] = __half_as_ushort(hi);
                    tl[sp4 + j][ci] = __half_as_ushort(lo);
                }
            }
        }
    }
    __syncthreads();

    const int ciQ = t & 15;
    const int rg  = t >> 4;
    #pragma unroll
    for (int si = 0; si < 4; si++) {
        int sp = si * 16 + rg;
        int yy = sp >> 3, xx = sp & 7;
        size_t obase = (size_t)(n * 64 + sp) * K9 + ci0 + ciQ * 4;
        #pragma unroll
        for (int r = 0; r < 9; r++) {
            int y = yy + r / 3 - 1, x = xx + r % 3 - 1;
            uint2 vh = make_uint2(0, 0), vl = make_uint2(0, 0);
            if ((unsigned)y < 8u && (unsigned)x < 8u) {
                int spp = y * 8 + x;
                vh = *(const uint2*)&th[spp][ciQ * 4];
                vl = *(const uint2*)&tl[spp][ciQ * 4];
            }
            *(uint2*)&g_Ah[obase + (size_t)r * 512] = vh;
            *(uint2*)&g_Al[obase + (size_t)r * 512] = vl;
        }
    }
}

// ---------------------------------------------------------------------------
// fp16x3 GEMM conv (R14 form: proven mainloop + staged coalesced epilogues).
// conv_in epilogue now writes SEPARATE hi/lo fp16 planes (same halves).
// ---------------------------------------------------------------------------
#define LDK2 20
#define STG_BYTES (4 * 128 * LDK2 * 4)
#define SMEM_BYTES (2 * STG_BYTES)

__device__ __forceinline__ void conv_fill(uint32_t base, int row0, int co0, int k0,
                                          int tid, const __half* gwh, const __half* gwl)
{
    #pragma unroll
    for (int h = 0; h < 2; h++) {
        int c = h * 256 + tid;
        int row = c >> 2, q = c & 3;
        uint32_t doff = (uint32_t)((row * LDK2 + q * 4) * 4);
        size_t aoff = (size_t)(row0 + row) * K9 + k0 + q * 8;
        size_t boff = (size_t)(co0 + row) * K9 + k0 + q * 8;
        cpa16(base + doff,         g_Ah + aoff);
        cpa16(base + 10240 + doff, g_Al + aoff);
        cpa16(base + 20480 + doff, gwh + boff);
        cpa16(base + 30720 + doff, gwl + boff);
    }
    asm volatile("cp.async.commit_group;" ::: "memory");
}

template <int CO, bool FIRST>
__global__ void __launch_bounds__(256, 2)
conv_f16_kernel(const __half* __restrict__ gwh,
                const __half* __restrict__ gwl,
                const float* __restrict__ bias,
                float* __restrict__ out)
{
    extern __shared__ uint32_t sm[];
    const uint32_t smb = (uint32_t)__cvta_generic_to_shared(sm);

    const int row0 = blockIdx.y * 128;
    const int co0  = blockIdx.x * 128;
    const int tid  = threadIdx.x;
    const int lane = tid & 31, wid = tid >> 5;
    const int rbase = (wid >> 1) * 32;
    const int cbase = (wid & 1) * 64;
    const int lg = lane >> 2, lt = lane & 3;

    const int aRow = lane & 15, aCol = (lane >> 4) * 4;
    const int bRow = ((lane >> 4) & 1) * 8 + (lane & 7);
    const int bCol = ((lane >> 3) & 1) * 4;

    float acc[2][8][4] = {};

    conv_fill(smb, row0, co0, 0, tid, gwh, gwl);

    const int NITER = K9 / 32;
    for (int it = 0; it < NITER; it++) {
        const int s = it & 1;
        asm volatile("cp.async.wait_group 0;" ::: "memory");
        __syncthreads();
        if (it + 1 < NITER)
            conv_fill(smb + (1 - s) * STG_BYTES, row0, co0, (it + 1) * 32, tid, gwh, gwl);

        const uint32_t base = smb + s * STG_BYTES;
        #pragma unroll
        for (int k16 = 0; k16 < 2; k16++) {
            const uint32_t ko = k16 * 8;
            uint32_t ah[2][4], al[2][4];
            #pragma unroll
            for (int mt = 0; mt < 2; mt++) {
                uint32_t aw = base + ((rbase + mt * 16 + aRow) * LDK2 + aCol + ko) * 4;
                ldsm4(ah[mt][0], ah[mt][1], ah[mt][2], ah[mt][3], aw);
                ldsm4(al[mt][0], al[mt][1], al[mt][2], al[mt][3], aw + 10240);
            }
            #pragma unroll
            for (int pr = 0; pr < 4; pr++) {
                uint32_t bw = base + 20480 +
                              ((cbase + pr * 16 + bRow) * LDK2 + bCol + ko) * 4;
                uint32_t bh0, bh1, bh2, bh3, bl0, bl1, bl2, bl3;
                ldsm4(bh0, bh1, bh2, bh3, bw);
                ldsm4(bl0, bl1, bl2, bl3, bw + 10240);
                mma_f16(acc[0][2 * pr],     ah[0], bh0, bh1);
                mma_f16(acc[1][2 * pr],     ah[1], bh0, bh1);
                mma_f16(acc[0][2 * pr + 1], ah[0], bh2, bh3);
                mma_f16(acc[1][2 * pr + 1], ah[1], bh2, bh3);
                mma_f16(acc[0][2 * pr],     ah[0], bl0, bl1);
                mma_f16(acc[1][2 * pr],     ah[1], bl0, bl1);
                mma_f16(acc[0][2 * pr + 1], ah[0], bl2, bl3);
                mma_f16(acc[1][2 * pr + 1], ah[1], bl2, bl3);
                mma_f16(acc[0][2 * pr],     al[0], bh0, bh1);
                mma_f16(acc[1][2 * pr],     al[1], bh0, bh1);
                mma_f16(acc[0][2 * pr + 1], al[0], bh2, bh3);
                mma_f16(acc[1][2 * pr + 1], al[1], bh2, bh3);
            }
        }
    }

    // ---- epilogue ----
    if (FIRST && co0 < 2048) {
        __syncthreads();
        #pragma unroll
        for (int mt = 0; mt < 2; mt++)
            #pragma unroll
            for (int nt = 0; nt < 8; nt++)
                #pragma unroll
                for (int cp = 0; cp < 4; cp++) {
                    int row = rbase + mt * 16 + lg + ((cp >= 2) ? 8 : 0);
                    int col = cbase + nt * 8 + lt * 2 + (cp & 1);
                    float v = acc[mt][nt][cp] + __ldg(&bias[co0 + col]);
                    sm[row * 136 + (col & 7) * 17 + (col >> 3)] = split_h2(v);
                }
        __syncthreads();
        const int e   = co0 >> 9;
        const int dd0 = (co0 & 511) >> 3;
        const int qd = tid >> 2, lt2 = tid & 3;
        #pragma unroll
        for (int it2 = 0; it2 < 16; it2++) {
            int task = it2 * 64 + qd;
            int row = task >> 3, hh = task & 7;
            int grow = row0 + row;
            int n = grow >> 6, sp = grow & 63;
            const uint32_t* src = &sm[row * 136 + hh * 17 + lt2 * 4];
            uint32_t s0 = src[0], s1 = src[1], s2 = src[2], s3 = src[3];
            uint2 vh = make_uint2(__byte_perm(s0, s1, 0x5410),
                                  __byte_perm(s2, s3, 0x5410));
            uint2 vl = make_uint2(__byte_perm(s0, s1, 0x7632),
                                  __byte_perm(s2, s3, 0x7632));
            size_t o = (((size_t)(e * BP + hh * 64 + sp)) * SEQ + n) * HD + dd0 + lt2 * 4;
            *(uint2*)&g_feats_h[o] = vh;
            *(uint2*)&g_feats_l[o] = vl;
        }
    } else if (FIRST) {
        #pragma unroll
        for (int mt = 0; mt < 2; mt++)
            #pragma unroll
            for (int nt = 0; nt < 8; nt++)
                #pragma unroll
                for (int cp = 0; cp < 4; cp++) {
                    int row = row0 + rbase + mt * 16 + lg + ((cp >= 2) ? 8 : 0);
                    int col = cbase + nt * 8 + lt * 2 + (cp & 1);
                    int co  = co0 + col;
                    float v = acc[mt][nt][cp] + __ldg(&bias[co]);
                    int n = row >> 6, sp = row & 63;
                    int dd = (co >> 3) & 63, hh = co & 7;
                    int bpi = hh * 64 + sp;
                    __half hi = __float2half_rn(v);
                    __half lo = __float2half_rn(v - __half2float(hi));
                    size_t o = ((size_t)bpi * HD + dd) * SEQ + n;
                    g_vT_h[o] = hi;
                    g_vT_l[o] = lo;
                }
    } else {
        __syncthreads();
        float* stgF = (float*)sm;
        #pragma unroll
        for (int mt = 0; mt < 2; mt++)
            #pragma unroll
            for (int nt = 0; nt < 8; nt++)
                #pragma unroll
                for (int cp = 0; cp < 4; cp++) {
                    int row = rbase + mt * 16 + lg + ((cp >= 2) ? 8 : 0);
                    int col = cbase + nt * 8 + lt * 2 + (cp & 1);
                    stgF[row * 133 + col] = acc[mt][nt][cp] + __ldg(&bias[co0 + col]);
                }
        __syncthreads();
        int n = tid >> 7, co = tid & 127;
        int gn = (row0 >> 6) + n;
        size_t obase = ((size_t)gn * CO + co0 + co) * 64;
        #pragma unroll
        for (int q = 0; q < 16; q++) {
            float4 v;
            v.x = stgF[(n * 64 + q * 4 + 0) * 133 + co];
            v.y = stgF[(n * 64 + q * 4 + 1) * 133 + co];
            v.z = stgF[(n * 64 + q * 4 + 2) * 133 + co];
            v.w = stgF[(n * 64 + q * 4 + 3) * 133 + co];
            *(float4*)&out[obase + q * 4] = v;
        }
    }
}

// ---------------------------------------------------------------------------
// Fused QK + dual softmax + agent blend + AV. 32-row q-tiles, 2 CTAs/SM.
// Q/K/V fills are now cp.async from pre-split hi/lo planes; K double-buffered
// (2 stages) with one barrier per chunk, conv-style.
// smem (words): Sf 0..12415 (32x388 f32), QH 12416(1152), QL 13568(1152),
// K stages: KH0 14720, KL0 17024, KH1 19328, KL1 21632; total 23936 w = 95744 B.
// ---------------------------------------------------------------------------
#define FA_SMEM 95744
#define SST 388
#define QH_OFF 12416
#define QL_OFF 13568
#define KS0_OFF 14720
#define KS1_OFF 19328
#define KHL_D   2304    // words between Kh and Kl within a stage

__global__ void __launch_bounds__(256, 2)
fused_attn_kernel(const float* __restrict__ am, const int* __restrict__ agent)
{
    extern __shared__ uint32_t sm[];
    float* Sf = (float*)sm;
    const uint32_t smb = (uint32_t)__cvta_generic_to_shared(sm);

    const int m0 = blockIdx.x * 32;
    const int bp = blockIdx.y;
    const int head = bp >> 6;
    const int tid = threadIdx.x, lane = tid & 31, wid = tid >> 5;
    const int wq   = (wid & 1) * 16;
    const int wcol = (wid >> 1) * 16;
    const int lg = lane >> 2, lt = lane & 3;
    const int aRow = lane & 15, aCol = (lane >> 4) * 4;
    const int bRow = ((lane >> 4) & 1) * 8 + (lane & 7);
    const int bCol = ((lane >> 3) & 1) * 4;

    // cp.async task mapping (row, 16B-chunk)
    const int qRowT = tid >> 3, qChT = tid & 7;   // Q: 256 tasks

    for (int v = 0; v < 2; v++) {
        const size_t qbase = (((size_t)(2 + v) * BP + bp) * SEQ + m0) * HD;
        const size_t kbase = ((size_t)v * BP + bp) * SEQ * HD;

        // Q fill (cp.async, once per v) + K chunk 0 into stage 0
        cpa16(smb + QH_OFF * 4 + qRowT * 144 + qChT * 16,
              g_feats_h + qbase + (size_t)qRowT * HD + qChT * 8);
        cpa16(smb + QL_OFF * 4 + qRowT * 144 + qChT * 16,
              g_feats_l + qbase + (size_t)qRowT * HD + qChT * 8);
        #pragma unroll
        for (int i = 0; i < 2; i++) {
            int task = i * 256 + tid;
            int row = task >> 3, ch = task & 7;
            size_t src = kbase + (size_t)row * HD + ch * 8;
            cpa16(smb + KS0_OFF * 4 + row * 144 + ch * 16, g_feats_h + src);
            cpa16(smb + (KS0_OFF + KHL_D) * 4 + row * 144 + ch * 16, g_feats_l + src);
        }
        asm volatile("cp.async.commit_group;" ::: "memory");

        for (int kc = 0; kc < 6; kc++) {
            asm volatile("cp.async.wait_group 0;" ::: "memory");
            __syncthreads();   // fill(kc) visible; MMA(kc-1) on other stage done
            if (kc + 1 < 6) {
                const uint32_t ks = ((kc + 1) & 1) ? KS1_OFF : KS0_OFF;
                #pragma unroll
                for (int i = 0; i < 2; i++) {
                    int task = i * 256 + tid;
                    int row = task >> 3, ch = task & 7;
                    size_t src = kbase + (size_t)((kc + 1) * 64 + row) * HD + ch * 8;
                    cpa16(smb + ks * 4 + row * 144 + ch * 16, g_feats_h + src);
                    cpa16(smb + (ks + KHL_D) * 4 + row * 144 + ch * 16, g_feats_l + src);
                }
                asm volatile("cp.async.commit_group;" ::: "memory");
            }

            const uint32_t ks = (kc & 1) ? KS1_OFF : KS0_OFF;
            float acc[2][4] = {};
            #pragma unroll
            for (int k16 = 0; k16 < 4; k16++) {
                const int ko = k16 * 8;
                uint32_t ah[4], al[4];
                uint32_t aw = smb + (QH_OFF + (wq + aRow) * 36 + aCol + ko) * 4;
                ldsm4(ah[0], ah[1], ah[2], ah[3], aw);
                ldsm4(al[0], al[1], al[2], al[3], aw + (QL_OFF - QH_OFF) * 4);
                uint32_t bw = smb + (ks + (wcol + bRow) * 36 + bCol + ko) * 4;
                uint32_t bh0, bh1, bh2, bh3, bl0, bl1, bl2, bl3;
                ldsm4(bh0, bh1, bh2, bh3, bw);
                ldsm4(bl0, bl1, bl2, bl3, bw + KHL_D * 4);
                mma_f16(acc[0], ah, bh0, bh1);
                mma_f16(acc[1], ah, bh2, bh3);
                mma_f16(acc[0], ah, bl0, bl1);
                mma_f16(acc[1], ah, bl2, bl3);
                mma_f16(acc[0], al, bh0, bh1);
                mma_f16(acc[1], al, bh2, bh3);
            }
            #pragma unroll
            for (int nt = 0; nt < 2; nt++) {
                #pragma unroll
                for (int cp = 0; cp < 4; cp++) {
                    int q   = wq + lg + ((cp >= 2) ? 8 : 0);
                    int col = kc * 64 + wcol + nt * 8 + lt * 2 + (cp & 1);
                    Sf[q * SST + col] = acc[nt][cp];
                }
            }
        }
        __syncthreads();

        #pragma unroll
        for (int r4 = 0; r4 < 4; r4++) {
            int row = wid * 4 + r4;
            int gq  = m0 + row;
            const float* amr = am + ((size_t)head * SEQ + gq) * SEQ;
            float e[12];
            float M = -1e30f;
            #pragma unroll
            for (int j = 0; j < 12; j++) {
                float s = Sf[row * SST + lane + 32 * j] * 0.125f + amr[lane + 32 * j];
                e[j] = s;
                M = fmaxf(M, s);
            }
            #pragma unroll
            for (int o = 16; o; o >>= 1) M = fmaxf(M, __shfl_xor_sync(~0u, M, o));
            float Z = 0.f;
            #pragma unroll
            for (int j = 0; j < 12; j++) { e[j] = __expf(e[j] - M); Z += e[j]; }
            #pragma unroll
            for (int o = 16; o; o >>= 1) Z += __shfl_xor_sync(~0u, Z, o);
            float rz = 1.f / Z;

            uint32_t* arow = g_attn + ((size_t)bp * SEQ + gq) * SEQ;
            if (v == 0) {
                #pragma unroll
                for (int j = 0; j < 12; j++)
                    arow[lane + 32 * j] = split_h2(e[j] * rz);
            } else {
                const int* mr = agent + ((size_t)head * SEQ + gq) * SEQ;
                #pragma unroll
                for (int j = 0; j < 12; j++) {
                    float a_same = unsplit_h2(arow[lane + 32 * j]);
                    float m = (float)mr[lane + 32 * j];
                    ((uint32_t*)Sf)[row * SST + lane + 32 * j] =
                        split_h2(m * a_same + (1.f - m) * e[j] * rz);
                }
            }
        }
    }

    // ---- AV phase: O[32 x 64] = attn(Sf packed) @ V, 6 chunks of k=64 ----
    const uint32_t* SfU = sm;
    const int hh2 = bp >> 6, p = bp & 63;
    const size_t vbase = (size_t)bp * HD * SEQ;

    float accv[2][4] = {};
    for (int kc = 0; kc < 6; kc++) {
        __syncthreads();   // kc=0: blend writes done; kc>0: prev MMA reads done
        // A-chunk planes (32 rows x 32 words) into QH/QL (from packed Sf)
        #pragma unroll
        for (int i = 0; i < 4; i++) {
            int task = i * 256 + tid;
            int row = task >> 5, w = task & 31;
            uint32_t p0 = SfU[row * SST + kc * 64 + 2 * w];
            uint32_t p1 = SfU[row * SST + kc * 64 + 2 * w + 1];
            sm[QH_OFF + row * 36 + w] = __byte_perm(p0, p1, 0x5410);
            sm[QL_OFF + row * 36 + w] = __byte_perm(p0, p1, 0x7632);
        }
        // V-chunk planes (64 dd x 8 chunks) into stage 0 via cp.async
        #pragma unroll
        for (int i = 0; i < 2; i++) {
            int task = i * 256 + tid;
            int dd = task >> 3, ch = task & 7;
            size_t src = vbase + (size_t)dd * SEQ + kc * 64 + ch * 8;
            cpa16(smb + KS0_OFF * 4 + dd * 144 + ch * 16, g_vT_h + src);
            cpa16(smb + (KS0_OFF + KHL_D) * 4 + dd * 144 + ch * 16, g_vT_l + src);
        }
        asm volatile("cp.async.commit_group;" ::: "memory");
        asm volatile("cp.async.wait_group 0;" ::: "memory");
        __syncthreads();

        #pragma unroll
        for (int k16 = 0; k16 < 4; k16++) {
            const int ko = k16 * 8;
            uint32_t ah[4], al[4];
            uint32_t aw = smb + (QH_OFF + (wq + aRow) * 36 + aCol + ko) * 4;
            ldsm4(ah[0], ah[1], ah[2], ah[3], aw);
            ldsm4(al[0], al[1], al[2], al[3], aw + (QL_OFF - QH_OFF) * 4);
            uint32_t bw = smb + (KS0_OFF + (wcol + bRow) * 36 + bCol + ko) * 4;
            uint32_t bh0, bh1, bh2, bh3, bl0, bl1, bl2, bl3;
            ldsm4(bh0, bh1, bh2, bh3, bw);
            ldsm4(bl0, bl1, bl2, bl3, bw + KHL_D * 4);
            mma_f16(accv[0], ah, bh0, bh1);
            mma_f16(accv[0], ah, bl0, bl1);
            mma_f16(accv[0], al, bh0, bh1);
            mma_f16(accv[1], ah, bh2, bh3);
            mma_f16(accv[1], ah, bl2, bl3);
            mma_f16(accv[1], al, bh2, bh3);
        }
    }

    #pragma unroll
    for (int nt = 0; nt < 2; nt++) {
        #pragma unroll
        for (int cp = 0; cp < 4; cp++) {
            int q  = m0 + wq + lg + ((cp >= 2) ? 8 : 0);
            int dd = wcol + nt * 8 + lt * 2 + (cp & 1);
            g_c2_hl[((size_t)q * CIN + (dd * 8 + hh2)) * 64 + p] =
                split_h2(accv[nt][cp]);
        }
    }
}

// ---------------------------------------------------------------------------
extern "C" void kernel_launch(void* const* d_in, const int* in_sizes, int n_in,
                              void* d_out, int out_size)
{
    const float* inp       = (const float*)d_in[0];
    const float* attn_mask = (const float*)d_in[1];
    const int*   agent     = (const int*)  d_in[2];
    const float* w_in      = (const float*)d_in[3];
    const float* b_in      = (const float*)d_in[4];
    const float* w_out     = (const float*)d_in[5];
    const float* b_out     = (const float*)d_in[6];
    float*       out       = (float*)d_out;

    __half *wh_in, *wl_in, *wh_out, *wl_out;
    cudaGetSymbolAddress((void**)&wh_in,  g_wh_in);
    cudaGetSymbolAddress((void**)&wl_in,  g_wl_in);
    cudaGetSymbolAddress((void**)&wh_out, g_wh_out);
    cudaGetSymbolAddress((void**)&wl_out, g_wl_out);

    cudaFuncSetAttribute(conv_f16_kernel<2560, true>,
                         cudaFuncAttributeMaxDynamicSharedMemorySize, SMEM_BYTES);
    cudaFuncSetAttribute(conv_f16_kernel<512, false>,
                         cudaFuncAttributeMaxDynamicSharedMemorySize, SMEM_BYTES);
    cudaFuncSetAttribute(fused_attn_kernel,
                         cudaFuncAttributeMaxDynamicSharedMemorySize, FA_SMEM);

    const int n_win  = 2560 * K9;
    const int n_wout = 512 * K9;
    split_w_kernel<<<(n_win + 255) / 256, 256>>>(w_in, wh_in, wl_in, n_win);
    split_w_kernel<<<(n_wout + 255) / 256, 256>>>(w_out, wh_out, wl_out, n_wout);

    // im2col expansion of raw input
    im2col_kernel<false><<<dim3(SEQ, 8), 256>>>(inp);

    // conv_in GEMM: M = 24576 (192 blocks of 128), N = 2560 (20 tiles)
    conv_f16_kernel<2560, true><<<dim3(20, 192), 256, SMEM_BYTES>>>(wh_in, wl_in, b_in, nullptr);

    // fused scores + dual softmax + agent blend + AV -> packed conv2 input
    fused_attn_kernel<<<dim3(12, BP), 256, FA_SMEM>>>(attn_mask, agent);

    // im2col expansion of attention output (packed source)
    im2col_kernel<true><<<dim3(SEQ, 8), 256>>>(nullptr);

    // conv_out GEMM: N = 512 (4 tiles)
    conv_f16_kernel<512, false><<<dim3(4, 192), 256, SMEM_BYTES>>>(wh_out, wl_out, b_out, out);
}

// round 17
// speedup vs baseline: 1.0206x; 1.0206x over previous
#include <cuda_runtime.h>
#include <cuda_fp16.h>
#include <cstdint>

#define SEQ 384
#define CIN 512
#define HW  64
#define NH  8
#define HD  64
#define K9  (CIN * 9)        // 4608
#define BP  512              // NH * HW batch-pairs
#define NROWS (SEQ * HW)     // 24576 GEMM rows
#define SS2 (SEQ * SEQ)      // 147456

// Scratch (device globals; no runtime allocation)
__device__ uint32_t g_feats_hl[(size_t)4 * BP * SEQ * HD];  // [e][bp][n][dd] packed(hi,lo)
__device__ uint32_t g_vT[(size_t)BP * HD * SEQ];            // [bp][dd][n]   packed(hi,lo)
__device__ uint32_t g_attn[(size_t)BP * SS2];               // v=0 a_same storage, packed
__device__ uint32_t g_c2_hl[(size_t)SEQ * CIN * HW];        // conv2 input, packed(hi,lo)
__device__ __half   g_Ah[(size_t)NROWS * K9];               // im2col hi plane (k' = r*512+ci)
__device__ __half   g_Al[(size_t)NROWS * K9];               // im2col lo plane
__device__ __half   g_wh_in[(size_t)2560 * K9];             // weights hi, k'-order
__device__ __half   g_wl_in[(size_t)2560 * K9];
__device__ __half   g_wh_out[(size_t)512 * K9];
__device__ __half   g_wl_out[(size_t)512 * K9];

// ---------------------------------------------------------------------------
// helpers
// ---------------------------------------------------------------------------
__device__ __forceinline__ uint32_t split_h2(float x)
{
    __half hi = __float2half_rn(x);
    __half lo = __float2half_rn(x - __half2float(hi));
    return (uint32_t)__half_as_ushort(hi) | ((uint32_t)__half_as_ushort(lo) << 16);
}
__device__ __forceinline__ float unsplit_h2(uint32_t p)
{
    return __half2float(__ushort_as_half((unsigned short)(p & 0xFFFF)))
         + __half2float(__ushort_as_half((unsigned short)(p >> 16)));
}

__device__ __forceinline__ void mma_f16(float c[4], const uint32_t a[4],
                                        uint32_t b0, uint32_t b1)
{
    asm volatile(
        "mma.sync.aligned.m16n8k16.row.col.f32.f16.f16.f32 "
        "{%0,%1,%2,%3}, {%4,%5,%6,%7}, {%8,%9}, {%0,%1,%2,%3};"
        : "+f"(c[0]), "+f"(c[1]), "+f"(c[2]), "+f"(c[3])
        : "r"(a[0]), "r"(a[1]), "r"(a[2]), "r"(a[3]), "r"(b0), "r"(b1));
}
__device__ __forceinline__ void ldsm4(uint32_t& r0, uint32_t& r1, uint32_t& r2,
                                      uint32_t& r3, uint32_t addr)
{
    asm volatile("ldmatrix.sync.aligned.m8n8.x4.shared.b16 {%0,%1,%2,%3}, [%4];"
                 : "=r"(r0), "=r"(r1), "=r"(r2), "=r"(r3) : "r"(addr));
}
__device__ __forceinline__ void cpa16(uint32_t dst, const void* src)
{
    asm volatile("cp.async.cg.shared.global [%0], [%1], 16;" :: "r"(dst), "l"(src));
}

// ---------------------------------------------------------------------------
// Weight split + permute to k' = r*512 + ci order.
// Single launch covers conv_in (i < n_in) and conv_out weights.
// ---------------------------------------------------------------------------
__global__ void split_w_all_kernel(const float* __restrict__ w_in,
                                   const float* __restrict__ w_out,
                                   int n_in, int n_total)
{
    int i = blockIdx.x * 256 + threadIdx.x;
    if (i >= n_total) return;
    const float* w;
    __half *wh, *wl;
    int j;
    if (i < n_in) {
        w = w_in;  wh = g_wh_in;  wl = g_wl_in;  j = i;
    } else {
        w = w_out; wh = g_wh_out; wl = g_wl_out; j = i - n_in;
    }
    int co = j / K9;
    int kn = j - co * K9;
    int r = kn >> 9, ci = kn & 511;
    float x = w[(size_t)co * K9 + ci * 9 + r];
    __half hi = __float2half_rn(x);
    wh[j] = hi;
    wl[j] = __float2half_rn(x - __half2float(hi));
}

// ---------------------------------------------------------------------------
// im2col expansion into hi/lo fp16 planes, k' = r*512 + ci.
// ---------------------------------------------------------------------------
template <bool PACKED>
__global__ __launch_bounds__(256) void im2col_kernel(const float* __restrict__ srcF)
{
    __shared__ ushort th[64][72];
    __shared__ ushort tl[64][72];
    const int n   = blockIdx.x;
    const int ci0 = blockIdx.y * 64;
    const int t   = threadIdx.x;

    {
        int sp4 = (t & 15) * 4;
        int ciL = t >> 4;
        #pragma unroll
        for (int pass = 0; pass < 4; pass++) {
            int ci = pass * 16 + ciL;
            if (PACKED) {
                uint4 w = *(const uint4*)(g_c2_hl + ((size_t)n * CIN + ci0 + ci) * 64 + sp4);
                uint32_t ws[4] = {w.x, w.y, w.z, w.w};
                #pragma unroll
                for (int j = 0; j < 4; j++) {
                    th[sp4 + j][ci] = (ushort)(ws[j] & 0xFFFF);
                    tl[sp4 + j][ci] = (ushort)(ws[j] >> 16);
                }
            } else {
                float4 v = *(const float4*)(srcF + ((size_t)n * CIN + ci0 + ci) * 64 + sp4);
                float vs[4] = {v.x, v.y, v.z, v.w};
                #pragma unroll
                for (int j = 0; j < 4; j++) {
                    __half hi = __float2half_rn(vs[j]);
                    __half lo = __float2half_rn(vs[j] - __half2float(hi));
                    th[sp4 + j][ci] = __half_as_ushort(hi);
                    tl[sp4 + j][ci] = __half_as_ushort(lo);
                }
            }
        }
    }
    __syncthreads();

    const int ciQ = t & 15;
    const int rg  = t >> 4;
    #pragma unroll
    for (int si = 0; si < 4; si++) {
        int sp = si * 16 + rg;
        int yy = sp >> 3, xx = sp & 7;
        size_t obase = (size_t)(n * 64 + sp) * K9 + ci0 + ciQ * 4;
        #pragma unroll
        for (int r = 0; r < 9; r++) {
            int y = yy + r / 3 - 1, x = xx + r % 3 - 1;
            uint2 vh = make_uint2(0, 0), vl = make_uint2(0, 0);
            if ((unsigned)y < 8u && (unsigned)x < 8u) {
                int spp = y * 8 + x;
                vh = *(const uint2*)&th[spp][ciQ * 4];
                vl = *(const uint2*)&tl[spp][ciQ * 4];
            }
            *(uint2*)&g_Ah[obase + (size_t)r * 512] = vh;
            *(uint2*)&g_Al[obase + (size_t)r * 512] = vl;
        }
    }
}

// ---------------------------------------------------------------------------
// fp16x3 GEMM conv (R14/R15 form: proven mainloop + staged coalesced epilogues).
// ---------------------------------------------------------------------------
#define LDK2 20
#define STG_BYTES (4 * 128 * LDK2 * 4)
#define SMEM_BYTES (2 * STG_BYTES)

__device__ __forceinline__ void conv_fill(uint32_t base, int row0, int co0, int k0,
                                          int tid, const __half* gwh, const __half* gwl)
{
    #pragma unroll
    for (int h = 0; h < 2; h++) {
        int c = h * 256 + tid;
        int row = c >> 2, q = c & 3;
        uint32_t doff = (uint32_t)((row * LDK2 + q * 4) * 4);
        size_t aoff = (size_t)(row0 + row) * K9 + k0 + q * 8;
        size_t boff = (size_t)(co0 + row) * K9 + k0 + q * 8;
        cpa16(base + doff,         g_Ah + aoff);
        cpa16(base + 10240 + doff, g_Al + aoff);
        cpa16(base + 20480 + doff, gwh + boff);
        cpa16(base + 30720 + doff, gwl + boff);
    }
    asm volatile("cp.async.commit_group;" ::: "memory");
}

template <int CO, bool FIRST>
__global__ void __launch_bounds__(256, 2)
conv_f16_kernel(const __half* __restrict__ gwh,
                const __half* __restrict__ gwl,
                const float* __restrict__ bias,
                float* __restrict__ out)
{
    extern __shared__ uint32_t sm[];
    const uint32_t smb = (uint32_t)__cvta_generic_to_shared(sm);

    const int row0 = blockIdx.y * 128;
    const int co0  = blockIdx.x * 128;
    const int tid  = threadIdx.x;
    const int lane = tid & 31, wid = tid >> 5;
    const int rbase = (wid >> 1) * 32;
    const int cbase = (wid & 1) * 64;
    const int lg = lane >> 2, lt = lane & 3;

    const int aRow = lane & 15, aCol = (lane >> 4) * 4;
    const int bRow = ((lane >> 4) & 1) * 8 + (lane & 7);
    const int bCol = ((lane >> 3) & 1) * 4;

    float acc[2][8][4] = {};

    conv_fill(smb, row0, co0, 0, tid, gwh, gwl);

    const int NITER = K9 / 32;
    for (int it = 0; it < NITER; it++) {
        const int s = it & 1;
        asm volatile("cp.async.wait_group 0;" ::: "memory");
        __syncthreads();
        if (it + 1 < NITER)
            conv_fill(smb + (1 - s) * STG_BYTES, row0, co0, (it + 1) * 32, tid, gwh, gwl);

        const uint32_t base = smb + s * STG_BYTES;
        #pragma unroll
        for (int k16 = 0; k16 < 2; k16++) {
            const uint32_t ko = k16 * 8;
            uint32_t ah[2][4], al[2][4];
            #pragma unroll
            for (int mt = 0; mt < 2; mt++) {
                uint32_t aw = base + ((rbase + mt * 16 + aRow) * LDK2 + aCol + ko) * 4;
                ldsm4(ah[mt][0], ah[mt][1], ah[mt][2], ah[mt][3], aw);
                ldsm4(al[mt][0], al[mt][1], al[mt][2], al[mt][3], aw + 10240);
            }
            #pragma unroll
            for (int pr = 0; pr < 4; pr++) {
                uint32_t bw = base + 20480 +
                              ((cbase + pr * 16 + bRow) * LDK2 + bCol + ko) * 4;
                uint32_t bh0, bh1, bh2, bh3, bl0, bl1, bl2, bl3;
                ldsm4(bh0, bh1, bh2, bh3, bw);
                ldsm4(bl0, bl1, bl2, bl3, bw + 10240);
                mma_f16(acc[0][2 * pr],     ah[0], bh0, bh1);
                mma_f16(acc[1][2 * pr],     ah[1], bh0, bh1);
                mma_f16(acc[0][2 * pr + 1], ah[0], bh2, bh3);
                mma_f16(acc[1][2 * pr + 1], ah[1], bh2, bh3);
                mma_f16(acc[0][2 * pr],     ah[0], bl0, bl1);
                mma_f16(acc[1][2 * pr],     ah[1], bl0, bl1);
                mma_f16(acc[0][2 * pr + 1], ah[0], bl2, bl3);
                mma_f16(acc[1][2 * pr + 1], ah[1], bl2, bl3);
                mma_f16(acc[0][2 * pr],     al[0], bh0, bh1);
                mma_f16(acc[1][2 * pr],     al[1], bh0, bh1);
                mma_f16(acc[0][2 * pr + 1], al[0], bh2, bh3);
                mma_f16(acc[1][2 * pr + 1], al[1], bh2, bh3);
            }
        }
    }

    // per-thread bias (2 columns), loaded once
    const int colA = cbase + lt * 2, colB = colA + 1;
    float biasA[8], biasB[8];
    #pragma unroll
    for (int nt = 0; nt < 8; nt++) {
        biasA[nt] = __ldg(&bias[co0 + ((nt * 8 + colA) & 127)]);
        biasB[nt] = __ldg(&bias[co0 + ((nt * 8 + colB) & 127)]);
    }

    // ---- epilogue ----
    if (FIRST && co0 < 2048) {
        __syncthreads();
        #pragma unroll
        for (int mt = 0; mt < 2; mt++)
            #pragma unroll
            for (int nt = 0; nt < 8; nt++)
                #pragma unroll
                for (int cp = 0; cp < 4; cp++) {
                    int row = rbase + mt * 16 + lg + ((cp >= 2) ? 8 : 0);
                    int col = cbase + nt * 8 + lt * 2 + (cp & 1);
                    float v = acc[mt][nt][cp] + ((cp & 1) ? biasB[nt] : biasA[nt]);
                    sm[row * 136 + (col & 7) * 17 + (col >> 3)] = split_h2(v);
                }
        __syncthreads();
        const int e   = co0 >> 9;
        const int dd0 = (co0 & 511) >> 3;
        const int qd = tid >> 2, lt2 = tid & 3;
        #pragma unroll
        for (int it2 = 0; it2 < 16; it2++) {
            int task = it2 * 64 + qd;
            int row = task >> 3, hh = task & 7;
            int grow = row0 + row;
            int n = grow >> 6, sp = grow & 63;
            const uint32_t* src = &sm[row * 136 + hh * 17 + lt2 * 4];
            uint4 v = make_uint4(src[0], src[1], src[2], src[3]);
            size_t o = (((size_t)(e * BP + hh * 64 + sp)) * SEQ + n) * HD + dd0 + lt2 * 4;
            *(uint4*)&g_feats_hl[o] = v;
        }
    } else if (FIRST) {
        #pragma unroll
        for (int mt = 0; mt < 2; mt++)
            #pragma unroll
            for (int nt = 0; nt < 8; nt++)
                #pragma unroll
                for (int cp = 0; cp < 4; cp++) {
                    int row = row0 + rbase + mt * 16 + lg + ((cp >= 2) ? 8 : 0);
                    int col = cbase + nt * 8 + lt * 2 + (cp & 1);
                    int co  = co0 + col;
                    float v = acc[mt][nt][cp] + ((cp & 1) ? biasB[nt] : biasA[nt]);
                    int n = row >> 6, sp = row & 63;
                    int dd = (co >> 3) & 63, hh = co & 7;
                    int bpi = hh * 64 + sp;
                    g_vT[((size_t)bpi * HD + dd) * SEQ + n] = split_h2(v);
                }
    } else {
        __syncthreads();
        float* stgF = (float*)sm;
        #pragma unroll
        for (int mt = 0; mt < 2; mt++)
            #pragma unroll
            for (int nt = 0; nt < 8; nt++)
                #pragma unroll
                for (int cp = 0; cp < 4; cp++) {
                    int row = rbase + mt * 16 + lg + ((cp >= 2) ? 8 : 0);
                    int col = cbase + nt * 8 + lt * 2 + (cp & 1);
                    stgF[row * 133 + col] = acc[mt][nt][cp] + ((cp & 1) ? biasB[nt] : biasA[nt]);
                }
        __syncthreads();
        int n = tid >> 7, co = tid & 127;
        int gn = (row0 >> 6) + n;
        size_t obase = ((size_t)gn * CO + co0 + co) * 64;
        #pragma unroll
        for (int q = 0; q < 16; q++) {
            float4 v;
            v.x = stgF[(n * 64 + q * 4 + 0) * 133 + co];
            v.y = stgF[(n * 64 + q * 4 + 1) * 133 + co];
            v.z = stgF[(n * 64 + q * 4 + 2) * 133 + co];
            v.w = stgF[(n * 64 + q * 4 + 3) * 133 + co];
            *(float4*)&out[obase + q * 4] = v;
        }
    }
}

// ---------------------------------------------------------------------------
// Fused QK + dual softmax + agent blend + AV (R15 form). 32-row q-tiles,
// 2 CTAs/SM. v=1 blend writes packed attn in place into Sf; AV from smem.
// ---------------------------------------------------------------------------
#define FA_SMEM 77312
#define SST 388
#define QH_OFF 12416
#define QL_OFF 13568
#define KH_OFF 14720
#define KL_OFF 17024

__global__ void __launch_bounds__(256, 2)
fused_attn_kernel(const float* __restrict__ am, const int* __restrict__ agent)
{
    extern __shared__ uint32_t sm[];
    float* Sf = (float*)sm;
    const uint32_t smb = (uint32_t)__cvta_generic_to_shared(sm);

    const int m0 = blockIdx.x * 32;
    const int bp = blockIdx.y;
    const int head = bp >> 6;
    const int tid = threadIdx.x, lane = tid & 31, wid = tid >> 5;
    const int wq   = (wid & 1) * 16;
    const int wcol = (wid >> 1) * 16;
    const int lg = lane >> 2, lt = lane & 3;
    const int aRow = lane & 15, aCol = (lane >> 4) * 4;
    const int bRow = ((lane >> 4) & 1) * 8 + (lane & 7);
    const int bCol = ((lane >> 3) & 1) * 4;

    for (int v = 0; v < 2; v++) {
        const uint32_t* Q = g_feats_hl + (((size_t)(2 + v) * BP + bp) * SEQ + m0) * HD;
        #pragma unroll
        for (int i = 0; i < 2; i++) {
            int lin = i * 256 + tid;
            int row = lin >> 4, q4 = lin & 15;
            uint4 w = *(const uint4*)(Q + (size_t)row * HD + q4 * 4);
            int o = row * 36 + q4 * 2;
            *(uint2*)&sm[QH_OFF + o] = make_uint2(__byte_perm(w.x, w.y, 0x5410),
                                                  __byte_perm(w.z, w.w, 0x5410));
            *(uint2*)&sm[QL_OFF + o] = make_uint2(__byte_perm(w.x, w.y, 0x7632),
                                                  __byte_perm(w.z, w.w, 0x7632));
        }

        const uint32_t* Kv = g_feats_hl + ((size_t)v * BP + bp) * SEQ * HD;
        for (int kc = 0; kc < 6; kc++) {
            __syncthreads();
            #pragma unroll
            for (int i = 0; i < 4; i++) {
                int lin = i * 256 + tid;
                int row = lin >> 4, q4 = lin & 15;
                uint4 w = *(const uint4*)(Kv + (size_t)(kc * 64 + row) * HD + q4 * 4);
                int o = row * 36 + q4 * 2;
                *(uint2*)&sm[KH_OFF + o] = make_uint2(__byte_perm(w.x, w.y, 0x5410),
                                                      __byte_perm(w.z, w.w, 0x5410));
                *(uint2*)&sm[KL_OFF + o] = make_uint2(__byte_perm(w.x, w.y, 0x7632),
                                                      __byte_perm(w.z, w.w, 0x7632));
            }
            __syncthreads();

            float acc[2][4] = {};
            #pragma unroll
            for (int k16 = 0; k16 < 4; k16++) {
                const int ko = k16 * 8;
                uint32_t ah[4], al[4];
                uint32_t aw = smb + (QH_OFF + (wq + aRow) * 36 + aCol + ko) * 4;
                ldsm4(ah[0], ah[1], ah[2], ah[3], aw);
                ldsm4(al[0], al[1], al[2], al[3], aw + (QL_OFF - QH_OFF) * 4);
                uint32_t bw = smb + (KH_OFF + (wcol + bRow) * 36 + bCol + ko) * 4;
                uint32_t bh0, bh1, bh2, bh3, bl0, bl1, bl2, bl3;
                ldsm4(bh0, bh1, bh2, bh3, bw);
                ldsm4(bl0, bl1, bl2, bl3, bw + (KL_OFF - KH_OFF) * 4);
                mma_f16(acc[0], ah, bh0, bh1);
                mma_f16(acc[1], ah, bh2, bh3);
                mma_f16(acc[0], ah, bl0, bl1);
                mma_f16(acc[1], ah, bl2, bl3);
                mma_f16(acc[0], al, bh0, bh1);
                mma_f16(acc[1], al, bh2, bh3);
            }
            #pragma unroll
            for (int nt = 0; nt < 2; nt++) {
                #pragma unroll
                for (int cp = 0; cp < 4; cp++) {
                    int q   = wq + lg + ((cp >= 2) ? 8 : 0);
                    int col = kc * 64 + wcol + nt * 8 + lt * 2 + (cp & 1);
                    Sf[q * SST + col] = acc[nt][cp];
                }
            }
        }
        __syncthreads();

        #pragma unroll
        for (int r4 = 0; r4 < 4; r4++) {
            int row = wid * 4 + r4;
            int gq  = m0 + row;
            const float* amr = am + ((size_t)head * SEQ + gq) * SEQ;
            float e[12];
            float M = -1e30f;
            #pragma unroll
            for (int j = 0; j < 12; j++) {
                float s = Sf[row * SST + lane + 32 * j] * 0.125f + amr[lane + 32 * j];
                e[j] = s;
                M = fmaxf(M, s);
            }
            #pragma unroll
            for (int o = 16; o; o >>= 1) M = fmaxf(M, __shfl_xor_sync(~0u, M, o));
            float Z = 0.f;
            #pragma unroll
            for (int j = 0; j < 12; j++) { e[j] = __expf(e[j] - M); Z += e[j]; }
            #pragma unroll
            for (int o = 16; o; o >>= 1) Z += __shfl_xor_sync(~0u, Z, o);
            float rz = 1.f / Z;

            uint32_t* arow = g_attn + ((size_t)bp * SEQ + gq) * SEQ;
            if (v == 0) {
                #pragma unroll
                for (int j = 0; j < 12; j++)
                    arow[lane + 32 * j] = split_h2(e[j] * rz);
            } else {
                const int* mr = agent + ((size_t)head * SEQ + gq) * SEQ;
                #pragma unroll
                for (int j = 0; j < 12; j++) {
                    float a_same = unsplit_h2(arow[lane + 32 * j]);
                    float m = (float)mr[lane + 32 * j];
                    ((uint32_t*)Sf)[row * SST + lane + 32 * j] =
                        split_h2(m * a_same + (1.f - m) * e[j] * rz);
                }
            }
        }
    }

    // ---- AV phase: O[32 x 64] = attn(Sf packed) @ V, 6 chunks of k=64 ----
    const uint32_t* SfU = sm;
    const uint32_t* Vp  = g_vT + (size_t)bp * HD * SEQ;
    const int hh2 = bp >> 6, p = bp & 63;

    float accv[2][4] = {};
    for (int kc = 0; kc < 6; kc++) {
        __syncthreads();
        #pragma unroll
        for (int i = 0; i < 4; i++) {
            int task = i * 256 + tid;
            int row = task >> 5, w = task & 31;
            uint32_t p0 = SfU[row * SST + kc * 64 + 2 * w];
            uint32_t p1 = SfU[row * SST + kc * 64 + 2 * w + 1];
            sm[QH_OFF + row * 36 + w] = __byte_perm(p0, p1, 0x5410);
            sm[QL_OFF + row * 36 + w] = __byte_perm(p0, p1, 0x7632);
        }
        #pragma unroll
        for (int i = 0; i < 8; i++) {
            int task = i * 256 + tid;
            int dd = task >> 5, w = task & 31;
            uint2 wv = *(const uint2*)(Vp + (size_t)dd * SEQ + kc * 64 + 2 * w);
            sm[KH_OFF + dd * 36 + w] = __byte_perm(wv.x, wv.y, 0x5410);
            sm[KL_OFF + dd * 36 + w] = __byte_perm(wv.x, wv.y, 0x7632);
        }
        __syncthreads();

        #pragma unroll
        for (int k16 = 0; k16 < 4; k16++) {
            const int ko = k16 * 8;
            uint32_t ah[4], al[4];
            uint32_t aw = smb + (QH_OFF + (wq + aRow) * 36 + aCol + ko) * 4;
            ldsm4(ah[0], ah[1], ah[2], ah[3], aw);
            ldsm4(al[0], al[1], al[2], al[3], aw + (QL_OFF - QH_OFF) * 4);
            uint32_t bw = smb + (KH_OFF + (wcol + bRow) * 36 + bCol + ko) * 4;
            uint32_t bh0, bh1, bh2, bh3, bl0, bl1, bl2, bl3;
            ldsm4(bh0, bh1, bh2, bh3, bw);
            ldsm4(bl0, bl1, bl2, bl3, bw + (KL_OFF - KH_OFF) * 4);
            mma_f16(accv[0], ah, bh0, bh1);
            mma_f16(accv[0], ah, bl0, bl1);
            mma_f16(accv[0], al, bh0, bh1);
            mma_f16(accv[1], ah, bh2, bh3);
            mma_f16(accv[1], ah, bl2, bl3);
            mma_f16(accv[1], al, bh2, bh3);
        }
    }

    #pragma unroll
    for (int nt = 0; nt < 2; nt++) {
        #pragma unroll
        for (int cp = 0; cp < 4; cp++) {
            int q  = m0 + wq + lg + ((cp >= 2) ? 8 : 0);
            int dd = wcol + nt * 8 + lt * 2 + (cp & 1);
            g_c2_hl[((size_t)q * CIN + (dd * 8 + hh2)) * 64 + p] =
                split_h2(accv[nt][cp]);
        }
    }
}

// ---------------------------------------------------------------------------
extern "C" void kernel_launch(void* const* d_in, const int* in_sizes, int n_in,
                              void* d_out, int out_size)
{
    const float* inp       = (const float*)d_in[0];
    const float* attn_mask = (const float*)d_in[1];
    const int*   agent     = (const int*)  d_in[2];
    const float* w_in      = (const float*)d_in[3];
    const float* b_in      = (const float*)d_in[4];
    const float* w_out     = (const float*)d_in[5];
    const float* b_out     = (const float*)d_in[6];
    float*       out       = (float*)d_out;

    __half *wh_in, *wl_in, *wh_out, *wl_out;
    cudaGetSymbolAddress((void**)&wh_in,  g_wh_in);
    cudaGetSymbolAddress((void**)&wl_in,  g_wl_in);
    cudaGetSymbolAddress((void**)&wh_out, g_wh_out);
    cudaGetSymbolAddress((void**)&wl_out, g_wl_out);

    cudaFuncSetAttribute(conv_f16_kernel<2560, true>,
                         cudaFuncAttributeMaxDynamicSharedMemorySize, SMEM_BYTES);
    cudaFuncSetAttribute(conv_f16_kernel<512, false>,
                         cudaFuncAttributeMaxDynamicSharedMemorySize, SMEM_BYTES);
    cudaFuncSetAttribute(fused_attn_kernel,
                         cudaFuncAttributeMaxDynamicSharedMemorySize, FA_SMEM);

    const int n_win   = 2560 * K9;
    const int n_wout  = 512 * K9;
    const int n_wtot  = n_win + n_wout;
    split_w_all_kernel<<<(n_wtot + 255) / 256, 256>>>(w_in, w_out, n_win, n_wtot);

    // im2col expansion of raw input
    im2col_kernel<false><<<dim3(SEQ, 8), 256>>>(inp);

    // conv_in GEMM: M = 24576 (192 blocks of 128), N = 2560 (20 tiles)
    conv_f16_kernel<2560, true><<<dim3(20, 192), 256, SMEM_BYTES>>>(wh_in, wl_in, b_in, nullptr);

    // fused scores + dual softmax + agent blend + AV -> packed conv2 input
    fused_attn_kernel<<<dim3(12, BP), 256, FA_SMEM>>>(attn_mask, agent);

    // im2col expansion of attention output (packed source)
    im2col_kernel<true><<<dim3(SEQ, 8), 256>>>(nullptr);

    // conv_out GEMM: N = 512 (4 tiles)
    conv_f16_kernel<512, false><<<dim3(4, 192), 256, SMEM_BYTES>>>(wh_out, wl_out, b_out, out);
}